// round 1
// baseline (speedup 1.0000x reference)
#include <cuda_runtime.h>

static constexpr int Bn   = 128;
static constexpr int Nn   = 256;
static constexpr int SMAX = 300;

// Per-batch partials: [0..Bn) = pair-loss sums, [Bn..2Bn) = setsize losses.
__device__ float g_partials[2 * Bn];

__device__ __forceinline__ float fsqrt_ap(float x) {
    float r;
    asm("sqrt.approx.f32 %0, %1;" : "=f"(r) : "f"(x));
    return r;
}

// ---------------------------------------------------------------------------
// Pair-loss kernel: one block per batch, 256 threads (one per particle row).
// pair_loss[i][j] = nll_class(j, cls_i) + nll_charge(j, chg_i)
//                 + ||ppos_i - fpos_j|| + ||pmom_i - fmom_j|| + (pe_i - fe_j)^2
// Row mins kept in registers; column mins in per-warp SMEM arrays with a
// staggered j = (t+k) & 255 schedule (distinct j per lane per step -> no race,
// __syncwarp bounds drift between steps).
// ---------------------------------------------------------------------------
__global__ void __launch_bounds__(256) pair_kernel(
    const int*   __restrict__ pcls,  const int*   __restrict__ pchg,
    const float* __restrict__ cl_logits, const float* __restrict__ ch_logits,
    const float* __restrict__ ppos,  const float* __restrict__ fpos,
    const float* __restrict__ pmom,  const float* __restrict__ fmom,
    const float* __restrict__ pe,    const float* __restrict__ fe)
{
    __shared__ float  s_nllc[Nn * 5];
    __shared__ float  s_nllq[Nn * 3];
    __shared__ float4 s_pf[Nn * 2];          // [j][0]=px,py,pz,mx  [j][1]=my,mz,e,0
    __shared__ float  s_colmin[8][Nn];       // per-warp column mins
    __shared__ float  s_red[8];

    const int b  = blockIdx.x;
    const int t  = threadIdx.x;
    const int gi = b * Nn + t;

    // pflow-side class NLL table (5 classes)
    {
        const float* cl = cl_logits + gi * 5;
        float x0 = cl[0], x1 = cl[1], x2 = cl[2], x3 = cl[3], x4 = cl[4];
        float m  = fmaxf(fmaxf(fmaxf(x0, x1), fmaxf(x2, x3)), x4);
        float s  = __expf(x0 - m) + __expf(x1 - m) + __expf(x2 - m)
                 + __expf(x3 - m) + __expf(x4 - m);
        float lse = m + __logf(s);
        s_nllc[t * 5 + 0] = lse - x0;
        s_nllc[t * 5 + 1] = lse - x1;
        s_nllc[t * 5 + 2] = lse - x2;
        s_nllc[t * 5 + 3] = lse - x3;
        s_nllc[t * 5 + 4] = lse - x4;
    }
    // pflow-side charge NLL table (3 classes)
    {
        const float* ch = ch_logits + gi * 3;
        float x0 = ch[0], x1 = ch[1], x2 = ch[2];
        float m  = fmaxf(fmaxf(x0, x1), x2);
        float s  = __expf(x0 - m) + __expf(x1 - m) + __expf(x2 - m);
        float lse = m + __logf(s);
        s_nllq[t * 3 + 0] = lse - x0;
        s_nllq[t * 3 + 1] = lse - x1;
        s_nllq[t * 3 + 2] = lse - x2;
    }
    // pflow-side geometry
    {
        float4 a, c;
        a.x = fpos[gi * 3 + 0]; a.y = fpos[gi * 3 + 1]; a.z = fpos[gi * 3 + 2];
        a.w = fmom[gi * 3 + 0]; c.x = fmom[gi * 3 + 1]; c.y = fmom[gi * 3 + 2];
        c.z = fe[gi];           c.w = 0.f;
        s_pf[t * 2 + 0] = a;
        s_pf[t * 2 + 1] = c;
    }
    #pragma unroll
    for (int w = 0; w < 8; w++) s_colmin[w][t] = 1e30f;

    // particle-side (this thread's row), kept in registers
    const int   cls = pcls[gi];
    const int   chg = pchg[gi];
    const float p0 = ppos[gi * 3 + 0], p1 = ppos[gi * 3 + 1], p2 = ppos[gi * 3 + 2];
    const float q0 = pmom[gi * 3 + 0], q1 = pmom[gi * 3 + 1], q2 = pmom[gi * 3 + 2];
    const float pen = pe[gi];

    __syncthreads();

    const int warp = t >> 5;
    float rowmin = 1e30f;
    int j = t;
    for (int k = 0; k < Nn; k++) {
        float4 a = s_pf[j * 2 + 0];
        float4 c = s_pf[j * 2 + 1];
        float dx = p0 - a.x, dy = p1 - a.y, dz = p2 - a.z;
        float d2p = dx * dx + dy * dy + dz * dz;
        float ex = q0 - a.w, ey = q1 - c.x, ez = q2 - c.y;
        float d2m = ex * ex + ey * ey + ez * ez;
        float de = pen - c.z;
        float loss = s_nllc[j * 5 + cls] + s_nllq[j * 3 + chg]
                   + fsqrt_ap(d2p) + fsqrt_ap(d2m) + de * de;
        rowmin = fminf(rowmin, loss);
        s_colmin[warp][j] = fminf(s_colmin[warp][j], loss);
        j = (j + 1) & (Nn - 1);
        __syncwarp();
    }
    __syncthreads();

    // reduce column mins across the 8 warps
    float cmin = s_colmin[0][t];
    #pragma unroll
    for (int w = 1; w < 8; w++) cmin = fminf(cmin, s_colmin[w][t]);

    // block-sum of (rowmin_i + colmin_j)
    float v = rowmin + cmin;
    #pragma unroll
    for (int o = 16; o; o >>= 1) v += __shfl_xor_sync(0xffffffffu, v, o);
    if ((t & 31) == 0) s_red[warp] = v;
    __syncthreads();
    if (t == 0) {
        float s = 0.f;
        #pragma unroll
        for (int w = 0; w < 8; w++) s += s_red[w];
        g_partials[b] = s;
    }
}

// ---------------------------------------------------------------------------
// Setsize kernel: one block per batch. Column means over N=256, then
// log-softmax over S_MAX=300 and pick n_particles[b].
// Thread t owns s = t and (if valid) s = t + 256.
// ---------------------------------------------------------------------------
__global__ void __launch_bounds__(256) setsize_kernel(
    const int*   __restrict__ n_part,
    const float* __restrict__ pred)
{
    __shared__ float s_red[8];
    __shared__ float s_x[512];

    const int b = blockIdx.x;
    const int t = threadIdx.x;
    const int warp = t >> 5, lane = t & 31;
    const float* base = pred + (size_t)b * Nn * SMAX;
    const bool has2 = (t + 256) < SMAX;

    float a1 = 0.f, a2 = 0.f;
    for (int n = 0; n < Nn; n++) {
        const float* r = base + n * SMAX;
        a1 += r[t];
        if (has2) a2 += r[t + 256];
    }
    a1 *= (1.f / Nn);
    a2 *= (1.f / Nn);
    s_x[t]       = a1;
    s_x[t + 256] = has2 ? a2 : -1e30f;

    // block max
    float v = fmaxf(a1, has2 ? a2 : -1e30f);
    #pragma unroll
    for (int o = 16; o; o >>= 1) v = fmaxf(v, __shfl_xor_sync(0xffffffffu, v, o));
    if (lane == 0) s_red[warp] = v;
    __syncthreads();
    float m = s_red[0];
    #pragma unroll
    for (int w = 1; w < 8; w++) m = fmaxf(m, s_red[w]);

    // block sum of exp(x - m)
    float e = __expf(a1 - m) + (has2 ? __expf(a2 - m) : 0.f);
    #pragma unroll
    for (int o = 16; o; o >>= 1) e += __shfl_xor_sync(0xffffffffu, e, o);
    __syncthreads();                 // s_red reuse
    if (lane == 0) s_red[warp] = e;
    __syncthreads();

    if (t == 0) {
        float S = 0.f;
        #pragma unroll
        for (int w = 0; w < 8; w++) S += s_red[w];
        float logZ = m + __logf(S);
        int nb = n_part[b];
        g_partials[Bn + b] = logZ - s_x[nb];   // -log_softmax at n_particles[b]
    }
}

// ---------------------------------------------------------------------------
// Final reduction: sum all 256 partials, divide by B, write the scalar.
// ---------------------------------------------------------------------------
__global__ void __launch_bounds__(256) final_kernel(float* __restrict__ out)
{
    __shared__ float s_red[8];
    const int t = threadIdx.x;
    float v = g_partials[t];
    #pragma unroll
    for (int o = 16; o; o >>= 1) v += __shfl_xor_sync(0xffffffffu, v, o);
    if ((t & 31) == 0) s_red[t >> 5] = v;
    __syncthreads();
    if (t == 0) {
        float s = 0.f;
        #pragma unroll
        for (int w = 0; w < 8; w++) s += s_red[w];
        out[0] = s * (1.0f / Bn);
    }
}

extern "C" void kernel_launch(void* const* d_in, const int* in_sizes, int n_in,
                              void* d_out, int out_size)
{
    const int*   pcls  = (const int*)  d_in[0];   // particle_class (B,N) int32
    const int*   pchg  = (const int*)  d_in[1];   // particle_charge (B,N) int32
    const int*   npart = (const int*)  d_in[2];   // n_particles (B,) int32
    const float* cl    = (const float*)d_in[3];   // pflow_class_logits (B,N,5)
    const float* ch    = (const float*)d_in[4];   // pflow_charge_logits (B,N,3)
    const float* ppos  = (const float*)d_in[5];   // particle_pos (B,N,3)
    const float* fpos  = (const float*)d_in[6];   // pflow_pos (B,N,3)
    const float* pmom  = (const float*)d_in[7];   // particle_mom (B,N,3)
    const float* fmom  = (const float*)d_in[8];   // pflow_mom (B,N,3)
    const float* pe    = (const float*)d_in[9];   // particle_energy (B,N)
    const float* fe    = (const float*)d_in[10];  // pflow_energy (B,N)
    const float* pred  = (const float*)d_in[11];  // predicted_setsizes (B,N,300)

    pair_kernel<<<Bn, 256>>>(pcls, pchg, cl, ch, ppos, fpos, pmom, fmom, pe, fe);
    setsize_kernel<<<Bn, 256>>>(npart, pred);
    final_kernel<<<1, 256>>>((float*)d_out);
}

// round 2
// speedup vs baseline: 1.5140x; 1.5140x over previous
#include <cuda_runtime.h>

static constexpr int Bn   = 128;
static constexpr int Nn   = 256;
static constexpr int SMAX = 300;

// Per-batch partials: [0..Bn) = pair-loss sums, [Bn..2Bn) = setsize losses.
__device__ float g_partials[2 * Bn];

__device__ __forceinline__ float fsqrt_ap(float x) {
    float r;
    asm("sqrt.approx.f32 %0, %1;" : "=f"(r) : "f"(x));
    return r;
}

struct PairSmem {
    float  nllc[Nn * 5];
    float  nllq[Nn * 3];
    float4 pfa[Nn];            // px, py, pz, mx
    float4 pfb[Nn];            // my, mz, e, 0
    float  colmin[8][Nn];      // per row-warp-group column mins
    float  rowmin[2][Nn];      // per j-half row mins
    float  red[16];
};
struct SetSmem {
    float x[SMAX];
    float red[16];
};
union FusedSmem { PairSmem p; SetSmem s; };

// ---------------------------------------------------------------------------
// Fused kernel, grid = 256 blocks x 512 threads.
//   blocks [0,128)   : pair loss for batch b = blockIdx.x
//   blocks [128,256) : setsize loss for batch b = blockIdx.x - 128
// Interleaving pair/setsize 148 apart in blockIdx puts one compute-bound and
// one HBM-bound block on each SM (classic bid%148 placement) for overlap.
// ---------------------------------------------------------------------------
__global__ void __launch_bounds__(512, 2) fused_kernel(
    const int*   __restrict__ pcls,  const int*   __restrict__ pchg,
    const int*   __restrict__ n_part,
    const float* __restrict__ cl_logits, const float* __restrict__ ch_logits,
    const float* __restrict__ ppos,  const float* __restrict__ fpos,
    const float* __restrict__ pmom,  const float* __restrict__ fmom,
    const float* __restrict__ pe,    const float* __restrict__ fe,
    const float* __restrict__ pred)
{
    __shared__ FusedSmem sm;
    const int t = threadIdx.x;

    if (blockIdx.x < Bn) {
        // ================= PAIR-LOSS BLOCK =================
        PairSmem& S = sm.p;
        const int b = blockIdx.x;

        // ---- stage pflow-side tables (threads 0..255, one per pflow j) ----
        if (t < Nn) {
            const int gj = b * Nn + t;
            {
                const float* cl = cl_logits + gj * 5;
                float x0 = cl[0], x1 = cl[1], x2 = cl[2], x3 = cl[3], x4 = cl[4];
                float m  = fmaxf(fmaxf(fmaxf(x0, x1), fmaxf(x2, x3)), x4);
                float s  = __expf(x0 - m) + __expf(x1 - m) + __expf(x2 - m)
                         + __expf(x3 - m) + __expf(x4 - m);
                float lse = m + __logf(s);
                S.nllc[t * 5 + 0] = lse - x0;
                S.nllc[t * 5 + 1] = lse - x1;
                S.nllc[t * 5 + 2] = lse - x2;
                S.nllc[t * 5 + 3] = lse - x3;
                S.nllc[t * 5 + 4] = lse - x4;
            }
            {
                const float* ch = ch_logits + gj * 3;
                float x0 = ch[0], x1 = ch[1], x2 = ch[2];
                float m  = fmaxf(fmaxf(x0, x1), x2);
                float s  = __expf(x0 - m) + __expf(x1 - m) + __expf(x2 - m);
                float lse = m + __logf(s);
                S.nllq[t * 3 + 0] = lse - x0;
                S.nllq[t * 3 + 1] = lse - x1;
                S.nllq[t * 3 + 2] = lse - x2;
            }
            {
                float4 a, c;
                a.x = fpos[gj * 3 + 0]; a.y = fpos[gj * 3 + 1]; a.z = fpos[gj * 3 + 2];
                a.w = fmom[gj * 3 + 0]; c.x = fmom[gj * 3 + 1]; c.y = fmom[gj * 3 + 2];
                c.z = fe[gj];           c.w = 0.f;
                S.pfa[t] = a;
                S.pfb[t] = c;
            }
        }

        // ---- particle-side (this thread's row) in registers ----
        const int h    = t >> 8;        // j-half: 0 or 1
        const int i    = t & (Nn - 1);  // row
        const int lane = t & 31;
        const int r    = (t >> 5) & 7;  // row-warp-group (rows r*32..r*32+31)
        const int gi   = b * Nn + i;

        const int   cls = pcls[gi];
        const int   chg = pchg[gi];
        const float p0 = ppos[gi * 3 + 0], p1 = ppos[gi * 3 + 1], p2 = ppos[gi * 3 + 2];
        const float q0 = pmom[gi * 3 + 0], q1 = pmom[gi * 3 + 1], q2 = pmom[gi * 3 + 2];
        const float pen = pe[gi];

        __syncthreads();

        // ---- main loop: uniform j per warp (broadcast loads), butterfly
        //      colmin, no barriers inside the loop ----
        float rowmin = 1e30f;
        const int jbase = h * (Nn / 2);
        #pragma unroll 4
        for (int jj = 0; jj < Nn / 2; jj++) {
            const int j = jbase + jj;
            float4 a = S.pfa[j];
            float4 c = S.pfb[j];
            float dx = p0 - a.x, dy = p1 - a.y, dz = p2 - a.z;
            float d2p = fmaf(dz, dz, fmaf(dy, dy, dx * dx));
            float ex = q0 - a.w, ey = q1 - c.x, ez = q2 - c.y;
            float d2m = fmaf(ez, ez, fmaf(ey, ey, ex * ex));
            float de  = pen - c.z;
            float base = S.nllc[j * 5 + cls] + S.nllq[j * 3 + chg];
            float loss = fmaf(de, de, base) + fsqrt_ap(d2p) + fsqrt_ap(d2m);

            rowmin = fminf(rowmin, loss);

            float cm = loss;
            cm = fminf(cm, __shfl_xor_sync(0xffffffffu, cm, 16));
            cm = fminf(cm, __shfl_xor_sync(0xffffffffu, cm, 8));
            cm = fminf(cm, __shfl_xor_sync(0xffffffffu, cm, 4));
            cm = fminf(cm, __shfl_xor_sync(0xffffffffu, cm, 2));
            cm = fminf(cm, __shfl_xor_sync(0xffffffffu, cm, 1));
            if (lane == 0) S.colmin[r][j] = cm;
        }
        S.rowmin[h][i] = rowmin;
        __syncthreads();

        // ---- combine: sum_i rowmin_i + sum_j colmin_j, block reduce ----
        if (t < Nn) {
            float rm = fminf(S.rowmin[0][t], S.rowmin[1][t]);
            float cm = S.colmin[0][t];
            #pragma unroll
            for (int w = 1; w < 8; w++) cm = fminf(cm, S.colmin[w][t]);
            float v = rm + cm;
            #pragma unroll
            for (int o = 16; o; o >>= 1) v += __shfl_xor_sync(0xffffffffu, v, o);
            if (lane == 0) S.red[t >> 5] = v;
        }
        __syncthreads();
        if (t == 0) {
            float s = 0.f;
            #pragma unroll
            for (int w = 0; w < 8; w++) s += S.red[w];
            g_partials[b] = s;
        }
    } else {
        // ================= SETSIZE BLOCK =================
        SetSmem& S = sm.s;
        const int b = blockIdx.x - Bn;
        const int warp = t >> 5, lane = t & 31;
        const bool act = t < SMAX;
        const float* base = pred + (size_t)b * Nn * SMAX;

        float a = 0.f;
        if (act) {
            #pragma unroll 4
            for (int n = 0; n < Nn; n++) a += base[n * SMAX + t];
            a *= (1.f / Nn);
            S.x[t] = a;
        }

        // block max
        float v = act ? a : -1e30f;
        #pragma unroll
        for (int o = 16; o; o >>= 1) v = fmaxf(v, __shfl_xor_sync(0xffffffffu, v, o));
        if (lane == 0) S.red[warp] = v;
        __syncthreads();
        float m = S.red[0];
        #pragma unroll
        for (int w = 1; w < 16; w++) m = fmaxf(m, S.red[w]);

        // block sum of exp(x - m)
        float e = act ? __expf(a - m) : 0.f;
        #pragma unroll
        for (int o = 16; o; o >>= 1) e += __shfl_xor_sync(0xffffffffu, e, o);
        __syncthreads();               // S.red reuse
        if (lane == 0) S.red[warp] = e;
        __syncthreads();

        if (t == 0) {
            float Z = 0.f;
            #pragma unroll
            for (int w = 0; w < 16; w++) Z += S.red[w];
            float logZ = m + __logf(Z);
            g_partials[Bn + b] = logZ - S.x[n_part[b]];
        }
    }
}

// ---------------------------------------------------------------------------
// Final reduction: sum all 256 partials, divide by B, write the scalar.
// ---------------------------------------------------------------------------
__global__ void __launch_bounds__(256) final_kernel(float* __restrict__ out)
{
    __shared__ float s_red[8];
    const int t = threadIdx.x;
    float v = g_partials[t];
    #pragma unroll
    for (int o = 16; o; o >>= 1) v += __shfl_xor_sync(0xffffffffu, v, o);
    if ((t & 31) == 0) s_red[t >> 5] = v;
    __syncthreads();
    if (t == 0) {
        float s = 0.f;
        #pragma unroll
        for (int w = 0; w < 8; w++) s += s_red[w];
        out[0] = s * (1.0f / Bn);
    }
}

extern "C" void kernel_launch(void* const* d_in, const int* in_sizes, int n_in,
                              void* d_out, int out_size)
{
    const int*   pcls  = (const int*)  d_in[0];   // particle_class (B,N) int32
    const int*   pchg  = (const int*)  d_in[1];   // particle_charge (B,N) int32
    const int*   npart = (const int*)  d_in[2];   // n_particles (B,) int32
    const float* cl    = (const float*)d_in[3];   // pflow_class_logits (B,N,5)
    const float* ch    = (const float*)d_in[4];   // pflow_charge_logits (B,N,3)
    const float* ppos  = (const float*)d_in[5];   // particle_pos (B,N,3)
    const float* fpos  = (const float*)d_in[6];   // pflow_pos (B,N,3)
    const float* pmom  = (const float*)d_in[7];   // particle_mom (B,N,3)
    const float* fmom  = (const float*)d_in[8];   // pflow_mom (B,N,3)
    const float* pe    = (const float*)d_in[9];   // particle_energy (B,N)
    const float* fe    = (const float*)d_in[10];  // pflow_energy (B,N)
    const float* pred  = (const float*)d_in[11];  // predicted_setsizes (B,N,300)

    fused_kernel<<<2 * Bn, 512>>>(pcls, pchg, npart, cl, ch,
                                  ppos, fpos, pmom, fmom, pe, fe, pred);
    final_kernel<<<1, 256>>>((float*)d_out);
}

// round 3
// speedup vs baseline: 1.9969x; 1.3190x over previous
#include <cuda_runtime.h>

static constexpr int Bn   = 128;
static constexpr int Nn   = 256;
static constexpr int SMAX = 300;

// Per-batch partials: [0..Bn) = pair-loss sums, [Bn..2Bn) = setsize losses.
__device__ float    g_partials[2 * Bn];
__device__ unsigned g_count = 0;

__device__ __forceinline__ float fsqrt_ap(float x) {
    float r;
    asm("sqrt.approx.f32 %0, %1;" : "=f"(r) : "f"(x));
    return r;
}

// Warp-wide min for NON-NEGATIVE floats via integer redux (bit ordering of
// non-negative IEEE floats matches unsigned ordering). One instruction
// instead of a 5-deep shfl butterfly.
__device__ __forceinline__ float warp_min_nonneg(float x) {
    unsigned u = __float_as_uint(x), r;
    asm("redux.sync.min.u32 %0, %1, 0xffffffff;" : "=r"(r) : "r"(u));
    return __uint_as_float(r);
}

struct PairSmem {
    float  nllc[Nn * 5];
    float  nllq[Nn * 3];
    float4 pfa[Nn];            // px, py, pz, mx
    float4 pfb[Nn];            // my, mz, e, 0
    float  colmin[8][Nn];      // per row-warp-group column mins
    float  rowmin[2][Nn];      // per j-half row mins
    float  red[16];
};
struct SetSmem {
    float x[SMAX];
    float red[16];
};
union FusedSmem { PairSmem p; SetSmem s; };

// ---------------------------------------------------------------------------
// Fully fused kernel, grid = 256 blocks x 512 threads.
//   blocks [0,128)   : pair loss for batch b = blockIdx.x
//   blocks [128,256) : setsize loss for batch b = blockIdx.x - 128
// The last block to finish (completion counter) sums all 256 partials and
// writes the scalar output — no separate reduction kernel.
// ---------------------------------------------------------------------------
__global__ void __launch_bounds__(512, 2) fused_kernel(
    const int*   __restrict__ pcls,  const int*   __restrict__ pchg,
    const int*   __restrict__ n_part,
    const float* __restrict__ cl_logits, const float* __restrict__ ch_logits,
    const float* __restrict__ ppos,  const float* __restrict__ fpos,
    const float* __restrict__ pmom,  const float* __restrict__ fmom,
    const float* __restrict__ pe,    const float* __restrict__ fe,
    const float* __restrict__ pred,
    float* __restrict__ out)
{
    __shared__ FusedSmem sm;
    __shared__ unsigned  s_islast;
    __shared__ float     s_fin[8];
    const int t = threadIdx.x;

    if (blockIdx.x < Bn) {
        // ================= PAIR-LOSS BLOCK =================
        PairSmem& S = sm.p;
        const int b = blockIdx.x;

        // ---- stage pflow-side tables (threads 0..255, one per pflow j) ----
        if (t < Nn) {
            const int gj = b * Nn + t;
            {
                const float* cl = cl_logits + gj * 5;
                float x0 = cl[0], x1 = cl[1], x2 = cl[2], x3 = cl[3], x4 = cl[4];
                float m  = fmaxf(fmaxf(fmaxf(x0, x1), fmaxf(x2, x3)), x4);
                float s  = __expf(x0 - m) + __expf(x1 - m) + __expf(x2 - m)
                         + __expf(x3 - m) + __expf(x4 - m);
                float lse = m + __logf(s);
                S.nllc[t * 5 + 0] = lse - x0;
                S.nllc[t * 5 + 1] = lse - x1;
                S.nllc[t * 5 + 2] = lse - x2;
                S.nllc[t * 5 + 3] = lse - x3;
                S.nllc[t * 5 + 4] = lse - x4;
            }
            {
                const float* ch = ch_logits + gj * 3;
                float x0 = ch[0], x1 = ch[1], x2 = ch[2];
                float m  = fmaxf(fmaxf(x0, x1), x2);
                float s  = __expf(x0 - m) + __expf(x1 - m) + __expf(x2 - m);
                float lse = m + __logf(s);
                S.nllq[t * 3 + 0] = lse - x0;
                S.nllq[t * 3 + 1] = lse - x1;
                S.nllq[t * 3 + 2] = lse - x2;
            }
            {
                float4 a, c;
                a.x = fpos[gj * 3 + 0]; a.y = fpos[gj * 3 + 1]; a.z = fpos[gj * 3 + 2];
                a.w = fmom[gj * 3 + 0]; c.x = fmom[gj * 3 + 1]; c.y = fmom[gj * 3 + 2];
                c.z = fe[gj];           c.w = 0.f;
                S.pfa[t] = a;
                S.pfb[t] = c;
            }
        }

        // ---- particle-side (this thread's row) in registers ----
        const int h    = t >> 8;        // j-half: 0 or 1
        const int i    = t & (Nn - 1);  // row
        const int lane = t & 31;
        const int r    = (t >> 5) & 7;  // row-warp-group (rows r*32..r*32+31)
        const int gi   = b * Nn + i;

        const int   cls = pcls[gi];
        const int   chg = pchg[gi];
        const float p0 = ppos[gi * 3 + 0], p1 = ppos[gi * 3 + 1], p2 = ppos[gi * 3 + 2];
        const float q0 = pmom[gi * 3 + 0], q1 = pmom[gi * 3 + 1], q2 = pmom[gi * 3 + 2];
        const float pen = pe[gi];

        __syncthreads();

        // ---- main loop: uniform j per warp (broadcast loads), single-redux
        //      colmin, no barriers inside the loop ----
        float rowmin = 1e30f;
        const int jbase = h * (Nn / 2);
        #pragma unroll 8
        for (int jj = 0; jj < Nn / 2; jj++) {
            const int j = jbase + jj;
            float4 a = S.pfa[j];
            float4 c = S.pfb[j];
            float dx = p0 - a.x, dy = p1 - a.y, dz = p2 - a.z;
            float d2p = fmaf(dz, dz, fmaf(dy, dy, dx * dx));
            float ex = q0 - a.w, ey = q1 - c.x, ez = q2 - c.y;
            float d2m = fmaf(ez, ez, fmaf(ey, ey, ex * ex));
            float de  = pen - c.z;
            float base = S.nllc[j * 5 + cls] + S.nllq[j * 3 + chg];
            float loss = fmaf(de, de, base) + fsqrt_ap(d2p) + fsqrt_ap(d2m);

            rowmin = fminf(rowmin, loss);

            float cm = warp_min_nonneg(loss);
            if (lane == 0) S.colmin[r][j] = cm;
        }
        S.rowmin[h][i] = rowmin;
        __syncthreads();

        // ---- combine: sum_i rowmin_i + sum_j colmin_j, block reduce ----
        if (t < Nn) {
            float rm = fminf(S.rowmin[0][t], S.rowmin[1][t]);
            float cm = S.colmin[0][t];
            #pragma unroll
            for (int w = 1; w < 8; w++) cm = fminf(cm, S.colmin[w][t]);
            float v = rm + cm;
            #pragma unroll
            for (int o = 16; o; o >>= 1) v += __shfl_xor_sync(0xffffffffu, v, o);
            if (lane == 0) S.red[t >> 5] = v;
        }
        __syncthreads();
        if (t == 0) {
            float s = 0.f;
            #pragma unroll
            for (int w = 0; w < 8; w++) s += S.red[w];
            g_partials[b] = s;
        }
    } else {
        // ================= SETSIZE BLOCK =================
        SetSmem& S = sm.s;
        const int b = blockIdx.x - Bn;
        const int warp = t >> 5, lane = t & 31;
        const bool act = t < SMAX;
        const float* base = pred + (size_t)b * Nn * SMAX;

        float a = 0.f;
        if (act) {
            #pragma unroll 4
            for (int n = 0; n < Nn; n++) a += base[n * SMAX + t];
            a *= (1.f / Nn);
            S.x[t] = a;
        }

        // block max
        float v = act ? a : -1e30f;
        #pragma unroll
        for (int o = 16; o; o >>= 1) v = fmaxf(v, __shfl_xor_sync(0xffffffffu, v, o));
        if (lane == 0) S.red[warp] = v;
        __syncthreads();
        float m = S.red[0];
        #pragma unroll
        for (int w = 1; w < 16; w++) m = fmaxf(m, S.red[w]);

        // block sum of exp(x - m)
        float e = act ? __expf(a - m) : 0.f;
        #pragma unroll
        for (int o = 16; o; o >>= 1) e += __shfl_xor_sync(0xffffffffu, e, o);
        __syncthreads();               // S.red reuse
        if (lane == 0) S.red[warp] = e;
        __syncthreads();

        if (t == 0) {
            float Z = 0.f;
            #pragma unroll
            for (int w = 0; w < 16; w++) Z += S.red[w];
            float logZ = m + __logf(Z);
            g_partials[Bn + b] = logZ - S.x[n_part[b]];
        }
    }

    // ================= COMPLETION-COUNTER FINAL REDUCTION =================
    if (t == 0) {
        __threadfence();
        unsigned old = atomicAdd(&g_count, 1u);
        s_islast = (old == 2u * Bn - 1u) ? 1u : 0u;
    }
    __syncthreads();
    if (s_islast) {
        if (t < 2 * Bn) {
            float v = ((volatile float*)g_partials)[t];
            #pragma unroll
            for (int o = 16; o; o >>= 1) v += __shfl_xor_sync(0xffffffffu, v, o);
            if ((t & 31) == 0) s_fin[t >> 5] = v;
        }
        __syncthreads();
        if (t == 0) {
            float s = 0.f;
            #pragma unroll
            for (int w = 0; w < 8; w++) s += s_fin[w];
            out[0] = s * (1.0f / Bn);
            g_count = 0;   // reset for next graph replay
        }
    }
}

extern "C" void kernel_launch(void* const* d_in, const int* in_sizes, int n_in,
                              void* d_out, int out_size)
{
    const int*   pcls  = (const int*)  d_in[0];   // particle_class (B,N) int32
    const int*   pchg  = (const int*)  d_in[1];   // particle_charge (B,N) int32
    const int*   npart = (const int*)  d_in[2];   // n_particles (B,) int32
    const float* cl    = (const float*)d_in[3];   // pflow_class_logits (B,N,5)
    const float* ch    = (const float*)d_in[4];   // pflow_charge_logits (B,N,3)
    const float* ppos  = (const float*)d_in[5];   // particle_pos (B,N,3)
    const float* fpos  = (const float*)d_in[6];   // pflow_pos (B,N,3)
    const float* pmom  = (const float*)d_in[7];   // particle_mom (B,N,3)
    const float* fmom  = (const float*)d_in[8];   // pflow_mom (B,N,3)
    const float* pe    = (const float*)d_in[9];   // particle_energy (B,N)
    const float* fe    = (const float*)d_in[10];  // pflow_energy (B,N)
    const float* pred  = (const float*)d_in[11];  // predicted_setsizes (B,N,300)

    fused_kernel<<<2 * Bn, 512>>>(pcls, pchg, npart, cl, ch,
                                  ppos, fpos, pmom, fmom, pe, fe, pred,
                                  (float*)d_out);
}